// round 16
// baseline (speedup 1.0000x reference)
#include <cuda_runtime.h>
#include <cuda_fp16.h>

// Problem constants
#define D_IN    4096
#define D_HID   2048
#define D_OUT   512
#define NBATCH  8192
#define NNZ1    32768
#define NNZ2    8192
#define SLOTS   64                   // padded edge slots per row (Poisson(16))
#define XPITCHB (NBATCH * 2)         // bytes per xt/g_h row (fp16)

// ---------------- scratch (__device__ globals) -------------------------------
__device__ __align__(16) float2 g_e1[D_HID * SLOTS];  // {w half2{w,w} bits, byteoff} 1MB
__device__ __align__(16) float2 g_e2[D_OUT * SLOTS];  // {w fp32, byteoff} 256KB
__device__ int g_c1[D_HID];
__device__ int g_c2[D_OUT];
__device__ __align__(128) __half g_xt[(size_t)D_IN * NBATCH];  // [col][batch] 64 MB
__device__ __align__(128) __half g_h [(size_t)D_HID * NBATCH]; // [row][batch] 32 MB

// ---------------- helpers ----------------------------------------------------
__device__ __forceinline__ unsigned H2U(__half2 h) { return *reinterpret_cast<unsigned*>(&h); }
__device__ __forceinline__ __half2  U2H(unsigned u) { return *reinterpret_cast<__half2*>(&u); }
__device__ __forceinline__ float sigf(float v) {
    return __fdividef(1.0f, 1.0f + __expf(-v));
}

// ---------------- k_xt: x [batch][col] f32 -> xt [col][batch] fp16 -----------
// 256-col x 64-batch tiles: each warp's read stream covers 1KB sequential per
// batch row for DRAM efficiency. Block (0,0) also zeroes the scatter counters.
__global__ __launch_bounds__(512) void k_xt(const float* __restrict__ x) {
    __shared__ unsigned tile[256 * 33];          // [col][batch-pair], 33792 B
    const int C0  = blockIdx.x * 256;
    const int B0  = blockIdx.y * 64;
    const int tid = threadIdx.x;

    if (C0 == 0 && B0 == 0) {
        for (int i = tid; i < D_HID; i += 512) g_c1[i] = 0;
        for (int i = tid; i < D_OUT; i += 512) g_c2[i] = 0;
    }

    const int bp = tid >> 4;                     // batch pair 0..31
    const int fc = tid & 15;                     // f4-col subindex 0..15
    const float4* rA = reinterpret_cast<const float4*>(
        x + (size_t)(B0 + 2 * bp) * D_IN + C0);
    const float4* rB = reinterpret_cast<const float4*>(
        x + (size_t)(B0 + 2 * bp + 1) * D_IN + C0);
    #pragma unroll
    for (int it = 0; it < 4; it++) {
        int    f4c = it * 16 + fc;               // 0..63 -> sequential 256B chunks
        float4 a = __ldg(rA + f4c);
        float4 b = __ldg(rB + f4c);
        int    c = f4c * 4;
        tile[(c + 0) * 33 + bp] = H2U(__floats2half2_rn(a.x, b.x));
        tile[(c + 1) * 33 + bp] = H2U(__floats2half2_rn(a.y, b.y));
        tile[(c + 2) * 33 + bp] = H2U(__floats2half2_rn(a.z, b.z));
        tile[(c + 3) * 33 + bp] = H2U(__floats2half2_rn(a.w, b.w));
    }
    __syncthreads();
    unsigned* xt32 = reinterpret_cast<unsigned*>(g_xt);
    const int w    = tid >> 5;
    const int lane = tid & 31;
    #pragma unroll
    for (int it = 0; it < 16; it++) {            // LDS bank (c+lane)%32: clean
        int c = it * 16 + w;                     // 0..255
        xt32[(size_t)(C0 + c) * (NBATCH / 2) + (B0 >> 1) + lane] = tile[c * 33 + lane];
    }
}

// ---------------- k_scat: both edge lists into padded slot matrix ------------
__global__ void k_scat(const float* __restrict__ w1, const int* __restrict__ rows1,
                       const int* __restrict__ cols1,
                       const float* __restrict__ w2, const int* __restrict__ rows2,
                       const int* __restrict__ cols2) {
    int e = blockIdx.x * blockDim.x + threadIdx.x;
    if (e < NNZ1) {
        int r = rows1[e];
        int p = atomicAdd(&g_c1[r], 1);
        __half2 wp = __float2half2_rn(w1[e]);
        if (p < SLOTS)
            g_e1[r * SLOTS + p] = make_float2(__uint_as_float(H2U(wp)),
                                              __int_as_float(cols1[e] * XPITCHB));
    }
    if (e < NNZ2) {
        int r = rows2[e];
        int p = atomicAdd(&g_c2[r], 1);
        if (p < SLOTS)
            g_e2[r * SLOTS + p] = make_float2(w2[e],
                                              __int_as_float(cols2[e] * XPITCHB));
    }
}

// ---------------- layer 1: lane = 8 batches, quad-stream edge loop -----------
__device__ __forceinline__ void gacc1(__half2* a, const char* xb,
                                      float wbits, float obits) {
    float4 v = __ldcg(reinterpret_cast<const float4*>(xb + __float_as_int(obits)));
    __half2 w = U2H(__float_as_uint(wbits));
    a[0] = __hfma2(w, *reinterpret_cast<__half2*>(&v.x), a[0]);
    a[1] = __hfma2(w, *reinterpret_cast<__half2*>(&v.y), a[1]);
    a[2] = __hfma2(w, *reinterpret_cast<__half2*>(&v.z), a[2]);
    a[3] = __hfma2(w, *reinterpret_cast<__half2*>(&v.w), a[3]);
}

__device__ __forceinline__ void tail_l1(__half2* A, const char* xb,
                                        const float4* E, int m, int ii,
                                        int r, int n) {
    for (int i = m; i < ii; i++) {
        float4 e = __ldg(E + i);
        gacc1(A, xb, e.x, e.y);
        gacc1(A, xb, e.z, e.w);
    }
    if (n & 1) {
        float2 e = __ldg(&g_e1[r * SLOTS + n - 1]);
        gacc1(A, xb, e.x, e.y);
    }
}

// Block = 512 thr, 2 CTAs/SM. Warp = 8 rows x 256 batches (lane=8 batches).
// Rows in 2 quad-groups; 4 interleaved streams, unroll 2.
__global__ __launch_bounds__(512, 2)
void k_l1(const float* __restrict__ b1) {
    const int w    = threadIdx.x >> 5;
    const int lane = threadIdx.x & 31;
    const int r0   = blockIdx.x * 128 + w * 8;
    const int b0   = blockIdx.y * 256;
    const char* xb = reinterpret_cast<const char*>(g_xt) + (size_t)(b0 + 8 * lane) * 2;

    __half2 acc[32];                             // 8 rows x 4 half2 (8 batches)
    #pragma unroll
    for (int j = 0; j < 8; j++) {
        __half2 bb = __float2half2_rn(__ldg(b1 + r0 + j));
        acc[4 * j] = bb; acc[4 * j + 1] = bb; acc[4 * j + 2] = bb; acc[4 * j + 3] = bb;
    }

    #pragma unroll 1
    for (int g = 0; g < 2; g++) {
        const int r = r0 + 4 * g;
        __half2* A = acc + 16 * g;
        int n0 = min(__ldg(&g_c1[r]),     SLOTS);
        int n1 = min(__ldg(&g_c1[r + 1]), SLOTS);
        int n2 = min(__ldg(&g_c1[r + 2]), SLOTS);
        int n3 = min(__ldg(&g_c1[r + 3]), SLOTS);
        const float4* E0 = reinterpret_cast<const float4*>(g_e1 + r * SLOTS);
        const float4* E1 = E0 + SLOTS / 2;
        const float4* E2 = E0 + SLOTS;
        const float4* E3 = E0 + 3 * (SLOTS / 2);
        const int i0 = n0 >> 1, i1 = n1 >> 1, i2 = n2 >> 1, i3 = n3 >> 1;
        const int m  = min(min(i0, i1), min(i2, i3));
        #pragma unroll 2
        for (int i = 0; i < m; i++) {
            float4 e0 = __ldg(E0 + i);
            float4 e1 = __ldg(E1 + i);
            float4 e2 = __ldg(E2 + i);
            float4 e3 = __ldg(E3 + i);
            gacc1(A,      xb, e0.x, e0.y); gacc1(A,      xb, e0.z, e0.w);
            gacc1(A + 4,  xb, e1.x, e1.y); gacc1(A + 4,  xb, e1.z, e1.w);
            gacc1(A + 8,  xb, e2.x, e2.y); gacc1(A + 8,  xb, e2.z, e2.w);
            gacc1(A + 12, xb, e3.x, e3.y); gacc1(A + 12, xb, e3.z, e3.w);
        }
        tail_l1(A,      xb, E0, m, i0, r,     n0);
        tail_l1(A + 4,  xb, E1, m, i1, r + 1, n1);
        tail_l1(A + 8,  xb, E2, m, i2, r + 2, n2);
        tail_l1(A + 12, xb, E3, m, i3, r + 3, n3);
    }

    #pragma unroll
    for (int j = 0; j < 8; j++) {                // sigmoid -> coalesced 16B stores
        float2 z0 = __half22float2(acc[4 * j]);
        float2 z1 = __half22float2(acc[4 * j + 1]);
        float2 z2 = __half22float2(acc[4 * j + 2]);
        float2 z3 = __half22float2(acc[4 * j + 3]);
        uint4 pk;
        pk.x = H2U(__floats2half2_rn(sigf(z0.x), sigf(z0.y)));
        pk.y = H2U(__floats2half2_rn(sigf(z1.x), sigf(z1.y)));
        pk.z = H2U(__floats2half2_rn(sigf(z2.x), sigf(z2.y)));
        pk.w = H2U(__floats2half2_rn(sigf(z3.x), sigf(z3.y)));
        *reinterpret_cast<uint4*>(&g_h[(size_t)(r0 + j) * NBATCH + b0 + 8 * lane]) = pk;
    }
}

// ---------------- layer 2: lane = 8 batches, fp32 acc, quad-stream -----------
// R14 warp shape (4 rows x 256 batches, 4 streams) kept; parallelism gained
// via 256-thread blocks: grid 16x32 = 512 blocks, up to 6 CTAs/SM.
__device__ __forceinline__ void gacc2(float* a, const char* hb, float wv, float obits) {
    float4 v  = __ldcg(reinterpret_cast<const float4*>(hb + __float_as_int(obits)));
    float2 f0 = __half22float2(*reinterpret_cast<__half2*>(&v.x));
    float2 f1 = __half22float2(*reinterpret_cast<__half2*>(&v.y));
    float2 f2 = __half22float2(*reinterpret_cast<__half2*>(&v.z));
    float2 f3 = __half22float2(*reinterpret_cast<__half2*>(&v.w));
    a[0] += wv * f0.x; a[1] += wv * f0.y;
    a[2] += wv * f1.x; a[3] += wv * f1.y;
    a[4] += wv * f2.x; a[5] += wv * f2.y;
    a[6] += wv * f3.x; a[7] += wv * f3.y;
}

__device__ __forceinline__ void tail_l2(float* A, const char* hb,
                                        const float4* E, int m, int ii,
                                        int r, int n) {
    for (int i = m; i < ii; i++) {
        float4 e = __ldg(E + i);
        gacc2(A, hb, e.x, e.y);
        gacc2(A, hb, e.z, e.w);
    }
    if (n & 1) {
        float2 e = __ldg(&g_e2[r * SLOTS + n - 1]);
        gacc2(A, hb, e.x, e.y);
    }
}

__global__ __launch_bounds__(256, 6)
void k_l2(const float* __restrict__ b2, float* __restrict__ out) {
    const int w    = threadIdx.x >> 5;
    const int lane = threadIdx.x & 31;
    const int r0   = blockIdx.x * 32 + w * 4;
    const int b0   = blockIdx.y * 256;
    const char* hb = reinterpret_cast<const char*>(g_h) + (size_t)(b0 + 8 * lane) * 2;

    float a[32];                                 // [row 0..3][batch 0..7]
    #pragma unroll
    for (int j = 0; j < 4; j++) {
        float b = __ldg(b2 + r0 + j);
        #pragma unroll
        for (int k = 0; k < 8; k++) a[8 * j + k] = b;
    }

    {
        int n0 = min(__ldg(&g_c2[r0]),     SLOTS);
        int n1 = min(__ldg(&g_c2[r0 + 1]), SLOTS);
        int n2 = min(__ldg(&g_c2[r0 + 2]), SLOTS);
        int n3 = min(__ldg(&g_c2[r0 + 3]), SLOTS);
        const float4* E0 = reinterpret_cast<const float4*>(g_e2 + r0 * SLOTS);
        const float4* E1 = E0 + SLOTS / 2;
        const float4* E2 = E0 + SLOTS;
        const float4* E3 = E0 + 3 * (SLOTS / 2);
        const int i0 = n0 >> 1, i1 = n1 >> 1, i2 = n2 >> 1, i3 = n3 >> 1;
        const int m  = min(min(i0, i1), min(i2, i3));
        #pragma unroll 2
        for (int i = 0; i < m; i++) {
            float4 e0 = __ldg(E0 + i);
            float4 e1 = __ldg(E1 + i);
            float4 e2 = __ldg(E2 + i);
            float4 e3 = __ldg(E3 + i);
            gacc2(a,      hb, e0.x, e0.y); gacc2(a,      hb, e0.z, e0.w);
            gacc2(a + 8,  hb, e1.x, e1.y); gacc2(a + 8,  hb, e1.z, e1.w);
            gacc2(a + 16, hb, e2.x, e2.y); gacc2(a + 16, hb, e2.z, e2.w);
            gacc2(a + 24, hb, e3.x, e3.y); gacc2(a + 24, hb, e3.z, e3.w);
        }
        tail_l2(a,      hb, E0, m, i0, r0,     n0);
        tail_l2(a + 8,  hb, E1, m, i1, r0 + 1, n1);
        tail_l2(a + 16, hb, E2, m, i2, r0 + 2, n2);
        tail_l2(a + 24, hb, E3, m, i3, r0 + 3, n3);
    }

    // per batch: 4 consecutive rows -> STG.128 (r0 multiple of 4 -> aligned)
    #pragma unroll
    for (int k = 0; k < 8; k++) {
        float* op = out + (size_t)(b0 + 8 * lane + k) * D_OUT + r0;
        *reinterpret_cast<float4*>(op) =
            make_float4(a[k], a[8 + k], a[16 + k], a[24 + k]);
    }
}

// ---------------- launch: 4 kernels, k_l2 at index 3 (profiler slot) ---------
extern "C" void kernel_launch(void* const* d_in, const int* in_sizes, int n_in,
                              void* d_out, int out_size) {
    const float* x     = (const float*)d_in[0];
    const float* w1    = (const float*)d_in[1];
    const float* b1    = (const float*)d_in[2];
    const float* w2    = (const float*)d_in[3];
    const float* b2    = (const float*)d_in[4];
    const int*   rows1 = (const int*)d_in[5];
    const int*   cols1 = (const int*)d_in[6];
    const int*   rows2 = (const int*)d_in[7];
    const int*   cols2 = (const int*)d_in[8];
    float*       out   = (float*)d_out;

    k_xt  <<<dim3(D_IN / 256, NBATCH / 64), 512>>>(x);
    k_scat<<<NNZ1 / 256, 256>>>(w1, rows1, cols1, w2, rows2, cols2);
    k_l1  <<<dim3(D_HID / 128, NBATCH / 256), 512>>>(b1);
    k_l2  <<<dim3(D_OUT / 32, NBATCH / 256), 256>>>(b2, out);
}

// round 17
// speedup vs baseline: 1.0978x; 1.0978x over previous
#include <cuda_runtime.h>
#include <cuda_fp16.h>

// Problem constants
#define D_IN    4096
#define D_HID   2048
#define D_OUT   512
#define NBATCH  8192
#define NNZ1    32768
#define NNZ2    8192
#define SLOTS   64                   // padded edge slots per row (Poisson(16))
#define XPITCHB (NBATCH * 2)         // bytes per xt/g_h row (fp16)

// ---------------- scratch (__device__ globals) -------------------------------
__device__ __align__(16) float2 g_e1[D_HID * SLOTS];  // {w half2{w,w} bits, byteoff} 1MB
__device__ __align__(16) float2 g_e2[D_OUT * SLOTS];  // {w fp32, byteoff} 256KB
__device__ int g_c1[D_HID];
__device__ int g_c2[D_OUT];
__device__ __align__(128) __half g_xt[(size_t)D_IN * NBATCH];  // [col][batch] 64 MB
__device__ __align__(128) __half g_h [(size_t)D_HID * NBATCH]; // [row][batch] 32 MB

// ---------------- helpers ----------------------------------------------------
__device__ __forceinline__ unsigned H2U(__half2 h) { return *reinterpret_cast<unsigned*>(&h); }
__device__ __forceinline__ __half2  U2H(unsigned u) { return *reinterpret_cast<__half2*>(&u); }
__device__ __forceinline__ float sigf(float v) {
    return __fdividef(1.0f, 1.0f + __expf(-v));
}

// ---------------- k_xt: x [batch][col] f32 -> xt [col][batch] fp16 -----------
// 256-col x 64-batch tiles: each warp's read stream covers 1KB sequential per
// batch row for DRAM efficiency. Block (0,0) also zeroes the scatter counters.
__global__ __launch_bounds__(512) void k_xt(const float* __restrict__ x) {
    __shared__ unsigned tile[256 * 33];          // [col][batch-pair], 33792 B
    const int C0  = blockIdx.x * 256;
    const int B0  = blockIdx.y * 64;
    const int tid = threadIdx.x;

    if (C0 == 0 && B0 == 0) {
        for (int i = tid; i < D_HID; i += 512) g_c1[i] = 0;
        for (int i = tid; i < D_OUT; i += 512) g_c2[i] = 0;
    }

    const int bp = tid >> 4;                     // batch pair 0..31
    const int fc = tid & 15;                     // f4-col subindex 0..15
    const float4* rA = reinterpret_cast<const float4*>(
        x + (size_t)(B0 + 2 * bp) * D_IN + C0);
    const float4* rB = reinterpret_cast<const float4*>(
        x + (size_t)(B0 + 2 * bp + 1) * D_IN + C0);
    #pragma unroll
    for (int it = 0; it < 4; it++) {
        int    f4c = it * 16 + fc;               // 0..63 -> sequential 256B chunks
        float4 a = __ldg(rA + f4c);
        float4 b = __ldg(rB + f4c);
        int    c = f4c * 4;
        tile[(c + 0) * 33 + bp] = H2U(__floats2half2_rn(a.x, b.x));
        tile[(c + 1) * 33 + bp] = H2U(__floats2half2_rn(a.y, b.y));
        tile[(c + 2) * 33 + bp] = H2U(__floats2half2_rn(a.z, b.z));
        tile[(c + 3) * 33 + bp] = H2U(__floats2half2_rn(a.w, b.w));
    }
    __syncthreads();
    unsigned* xt32 = reinterpret_cast<unsigned*>(g_xt);
    const int w    = tid >> 5;
    const int lane = tid & 31;
    #pragma unroll
    for (int it = 0; it < 16; it++) {            // LDS bank (c+lane)%32: clean
        int c = it * 16 + w;                     // 0..255
        xt32[(size_t)(C0 + c) * (NBATCH / 2) + (B0 >> 1) + lane] = tile[c * 33 + lane];
    }
}

// ---------------- k_scat: both edge lists into padded slot matrix ------------
__global__ void k_scat(const float* __restrict__ w1, const int* __restrict__ rows1,
                       const int* __restrict__ cols1,
                       const float* __restrict__ w2, const int* __restrict__ rows2,
                       const int* __restrict__ cols2) {
    int e = blockIdx.x * blockDim.x + threadIdx.x;
    if (e < NNZ1) {
        int r = rows1[e];
        int p = atomicAdd(&g_c1[r], 1);
        __half2 wp = __float2half2_rn(w1[e]);
        if (p < SLOTS)
            g_e1[r * SLOTS + p] = make_float2(__uint_as_float(H2U(wp)),
                                              __int_as_float(cols1[e] * XPITCHB));
    }
    if (e < NNZ2) {
        int r = rows2[e];
        int p = atomicAdd(&g_c2[r], 1);
        if (p < SLOTS)
            g_e2[r * SLOTS + p] = make_float2(w2[e],
                                              __int_as_float(cols2[e] * XPITCHB));
    }
}

// ---------------- layer 1: lane = 8 batches, quad-stream edge loop -----------
__device__ __forceinline__ void gacc1(__half2* a, const char* xb,
                                      float wbits, float obits) {
    float4 v = __ldcg(reinterpret_cast<const float4*>(xb + __float_as_int(obits)));
    __half2 w = U2H(__float_as_uint(wbits));
    a[0] = __hfma2(w, *reinterpret_cast<__half2*>(&v.x), a[0]);
    a[1] = __hfma2(w, *reinterpret_cast<__half2*>(&v.y), a[1]);
    a[2] = __hfma2(w, *reinterpret_cast<__half2*>(&v.z), a[2]);
    a[3] = __hfma2(w, *reinterpret_cast<__half2*>(&v.w), a[3]);
}

__device__ __forceinline__ void tail_l1(__half2* A, const char* xb,
                                        const float4* E, int m, int ii,
                                        int r, int n) {
    for (int i = m; i < ii; i++) {
        float4 e = __ldg(E + i);
        gacc1(A, xb, e.x, e.y);
        gacc1(A, xb, e.z, e.w);
    }
    if (n & 1) {
        float2 e = __ldg(&g_e1[r * SLOTS + n - 1]);
        gacc1(A, xb, e.x, e.y);
    }
}

// Block = 512 thr, 2 CTAs/SM (64 regs). Warp = 8 rows x 256 batches (lane=8).
// Rows in 2 quad-groups; 4 interleaved streams, unroll 2.
__global__ __launch_bounds__(512, 2)
void k_l1(const float* __restrict__ b1) {
    const int w    = threadIdx.x >> 5;
    const int lane = threadIdx.x & 31;
    const int r0   = blockIdx.x * 128 + w * 8;
    const int b0   = blockIdx.y * 256;
    const char* xb = reinterpret_cast<const char*>(g_xt) + (size_t)(b0 + 8 * lane) * 2;

    __half2 acc[32];                             // 8 rows x 4 half2 (8 batches)
    #pragma unroll
    for (int j = 0; j < 8; j++) {
        __half2 bb = __float2half2_rn(__ldg(b1 + r0 + j));
        acc[4 * j] = bb; acc[4 * j + 1] = bb; acc[4 * j + 2] = bb; acc[4 * j + 3] = bb;
    }

    #pragma unroll 1
    for (int g = 0; g < 2; g++) {
        const int r = r0 + 4 * g;
        __half2* A = acc + 16 * g;
        int n0 = min(__ldg(&g_c1[r]),     SLOTS);
        int n1 = min(__ldg(&g_c1[r + 1]), SLOTS);
        int n2 = min(__ldg(&g_c1[r + 2]), SLOTS);
        int n3 = min(__ldg(&g_c1[r + 3]), SLOTS);
        const float4* E0 = reinterpret_cast<const float4*>(g_e1 + r * SLOTS);
        const float4* E1 = E0 + SLOTS / 2;
        const float4* E2 = E0 + SLOTS;
        const float4* E3 = E0 + 3 * (SLOTS / 2);
        const int i0 = n0 >> 1, i1 = n1 >> 1, i2 = n2 >> 1, i3 = n3 >> 1;
        const int m  = min(min(i0, i1), min(i2, i3));
        #pragma unroll 2
        for (int i = 0; i < m; i++) {
            float4 e0 = __ldg(E0 + i);
            float4 e1 = __ldg(E1 + i);
            float4 e2 = __ldg(E2 + i);
            float4 e3 = __ldg(E3 + i);
            gacc1(A,      xb, e0.x, e0.y); gacc1(A,      xb, e0.z, e0.w);
            gacc1(A + 4,  xb, e1.x, e1.y); gacc1(A + 4,  xb, e1.z, e1.w);
            gacc1(A + 8,  xb, e2.x, e2.y); gacc1(A + 8,  xb, e2.z, e2.w);
            gacc1(A + 12, xb, e3.x, e3.y); gacc1(A + 12, xb, e3.z, e3.w);
        }
        tail_l1(A,      xb, E0, m, i0, r,     n0);
        tail_l1(A + 4,  xb, E1, m, i1, r + 1, n1);
        tail_l1(A + 8,  xb, E2, m, i2, r + 2, n2);
        tail_l1(A + 12, xb, E3, m, i3, r + 3, n3);
    }

    #pragma unroll
    for (int j = 0; j < 8; j++) {                // sigmoid -> coalesced 16B stores
        float2 z0 = __half22float2(acc[4 * j]);
        float2 z1 = __half22float2(acc[4 * j + 1]);
        float2 z2 = __half22float2(acc[4 * j + 2]);
        float2 z3 = __half22float2(acc[4 * j + 3]);
        uint4 pk;
        pk.x = H2U(__floats2half2_rn(sigf(z0.x), sigf(z0.y)));
        pk.y = H2U(__floats2half2_rn(sigf(z1.x), sigf(z1.y)));
        pk.z = H2U(__floats2half2_rn(sigf(z2.x), sigf(z2.y)));
        pk.w = H2U(__floats2half2_rn(sigf(z3.x), sigf(z3.y)));
        *reinterpret_cast<uint4*>(&g_h[(size_t)(r0 + j) * NBATCH + b0 + 8 * lane]) = pk;
    }
}

// ---------------- layer 2: lane = 4 batches (batch-split), fp32 acc ----------
// R14 warp/stream shape kept (4 rows, quad-stream, 512 thr, (512,2) -> 64 regs);
// parallelism from batch split: tile = 128 batches -> grid 8 x 64 = 512 blocks.
__device__ __forceinline__ void gacc2(float* a, const char* hb, float wv, float obits) {
    float2 v  = __ldcg(reinterpret_cast<const float2*>(hb + __float_as_int(obits)));
    float2 f0 = __half22float2(*reinterpret_cast<__half2*>(&v.x));
    float2 f1 = __half22float2(*reinterpret_cast<__half2*>(&v.y));
    a[0] += wv * f0.x; a[1] += wv * f0.y;
    a[2] += wv * f1.x; a[3] += wv * f1.y;
}

__device__ __forceinline__ void tail_l2(float* A, const char* hb,
                                        const float4* E, int m, int ii,
                                        int r, int n) {
    for (int i = m; i < ii; i++) {
        float4 e = __ldg(E + i);
        gacc2(A, hb, e.x, e.y);
        gacc2(A, hb, e.z, e.w);
    }
    if (n & 1) {
        float2 e = __ldg(&g_e2[r * SLOTS + n - 1]);
        gacc2(A, hb, e.x, e.y);
    }
}

__global__ __launch_bounds__(512, 2)
void k_l2(const float* __restrict__ b2, float* __restrict__ out) {
    const int w    = threadIdx.x >> 5;
    const int lane = threadIdx.x & 31;
    const int r0   = blockIdx.x * 64 + w * 4;
    const int b0   = blockIdx.y * 128;
    const char* hb = reinterpret_cast<const char*>(g_h) + (size_t)(b0 + 4 * lane) * 2;

    float a[16];                                 // [row 0..3][batch 0..3]
    #pragma unroll
    for (int j = 0; j < 4; j++) {
        float b = __ldg(b2 + r0 + j);
        #pragma unroll
        for (int k = 0; k < 4; k++) a[4 * j + k] = b;
    }

    {
        int n0 = min(__ldg(&g_c2[r0]),     SLOTS);
        int n1 = min(__ldg(&g_c2[r0 + 1]), SLOTS);
        int n2 = min(__ldg(&g_c2[r0 + 2]), SLOTS);
        int n3 = min(__ldg(&g_c2[r0 + 3]), SLOTS);
        const float4* E0 = reinterpret_cast<const float4*>(g_e2 + r0 * SLOTS);
        const float4* E1 = E0 + SLOTS / 2;
        const float4* E2 = E0 + SLOTS;
        const float4* E3 = E0 + 3 * (SLOTS / 2);
        const int i0 = n0 >> 1, i1 = n1 >> 1, i2 = n2 >> 1, i3 = n3 >> 1;
        const int m  = min(min(i0, i1), min(i2, i3));
        #pragma unroll 2
        for (int i = 0; i < m; i++) {            // 4 edge LDG + 16 gather LDG in flight
            float4 e0 = __ldg(E0 + i);
            float4 e1 = __ldg(E1 + i);
            float4 e2 = __ldg(E2 + i);
            float4 e3 = __ldg(E3 + i);
            gacc2(a,      hb, e0.x, e0.y); gacc2(a,      hb, e0.z, e0.w);
            gacc2(a + 4,  hb, e1.x, e1.y); gacc2(a + 4,  hb, e1.z, e1.w);
            gacc2(a + 8,  hb, e2.x, e2.y); gacc2(a + 8,  hb, e2.z, e2.w);
            gacc2(a + 12, hb, e3.x, e3.y); gacc2(a + 12, hb, e3.z, e3.w);
        }
        tail_l2(a,      hb, E0, m, i0, r0,     n0);
        tail_l2(a + 4,  hb, E1, m, i1, r0 + 1, n1);
        tail_l2(a + 8,  hb, E2, m, i2, r0 + 2, n2);
        tail_l2(a + 12, hb, E3, m, i3, r0 + 3, n3);
    }

    // per batch: 4 consecutive rows -> STG.128 (r0 multiple of 4 -> aligned)
    #pragma unroll
    for (int k = 0; k < 4; k++) {
        float* op = out + (size_t)(b0 + 4 * lane + k) * D_OUT + r0;
        *reinterpret_cast<float4*>(op) =
            make_float4(a[k], a[4 + k], a[8 + k], a[12 + k]);
    }
}

// ---------------- launch: 4 kernels, k_l2 at index 3 (profiler slot) ---------
extern "C" void kernel_launch(void* const* d_in, const int* in_sizes, int n_in,
                              void* d_out, int out_size) {
    const float* x     = (const float*)d_in[0];
    const float* w1    = (const float*)d_in[1];
    const float* b1    = (const float*)d_in[2];
    const float* w2    = (const float*)d_in[3];
    const float* b2    = (const float*)d_in[4];
    const int*   rows1 = (const int*)d_in[5];
    const int*   cols1 = (const int*)d_in[6];
    const int*   rows2 = (const int*)d_in[7];
    const int*   cols2 = (const int*)d_in[8];
    float*       out   = (float*)d_out;

    k_xt  <<<dim3(D_IN / 256, NBATCH / 64), 512>>>(x);
    k_scat<<<NNZ1 / 256, 256>>>(w1, rows1, cols1, w2, rows2, cols2);
    k_l1  <<<dim3(D_HID / 128, NBATCH / 256), 512>>>(b1);
    k_l2  <<<dim3(D_OUT / 64, NBATCH / 128), 512>>>(b2, out);
}